// round 2
// baseline (speedup 1.0000x reference)
#include <cuda_runtime.h>
#include <cstdint>
#include <cstddef>

// ============================ problem constants ============================
#define D_IN   1024
#define NH1    4096
#define NH2    512
#define D_OUT  256
#define NROWS  16384

// ============================ tiling =======================================
#define BM 256
#define BN 128
#define BK 32
#define STAGE_F 12288              // floats per stage: (BM+BN)*BK = (256+128)*32
#define STAGE_B 49152              // bytes per stage

// ============================ scratch ======================================
__device__ __align__(1024) float g_x2[NROWS * NH2];   // grouped-layer output

// ============================ device helpers ===============================
__device__ __forceinline__ uint32_t sm32(const void* p) {
    uint32_t a;
    asm("{ .reg .u64 t; cvta.to.shared.u64 t, %1; cvt.u32.u64 %0, t; }"
        : "=r"(a) : "l"(p));
    return a;
}
__device__ __forceinline__ void cpa16(uint32_t d, const void* s) {
    asm volatile("cp.async.cg.shared.global [%0], [%1], 16;" :: "r"(d), "l"(s));
}
#define CP_COMMIT() asm volatile("cp.async.commit_group;" ::: "memory")
#define CP_WAIT1()  asm volatile("cp.async.wait_group 1;" ::: "memory")

__device__ __forceinline__ void ldsm4(uint32_t* d, uint32_t a) {
    asm volatile("ldmatrix.sync.aligned.m8n8.x4.shared.b16 {%0,%1,%2,%3}, [%4];"
        : "=r"(d[0]), "=r"(d[1]), "=r"(d[2]), "=r"(d[3]) : "r"(a));
}
__device__ __forceinline__ void mma8(float* c, const uint32_t* a, const uint32_t* b) {
    asm volatile("mma.sync.aligned.m16n8k8.row.col.f32.tf32.tf32.f32 "
        "{%0,%1,%2,%3}, {%4,%5,%6,%7}, {%8,%9}, {%0,%1,%2,%3};"
        : "+f"(c[0]), "+f"(c[1]), "+f"(c[2]), "+f"(c[3])
        : "r"(a[0]), "r"(a[1]), "r"(a[2]), "r"(a[3]), "r"(b[0]), "r"(b[1]));
}
__device__ __forceinline__ float rna_tf32(float v) {
    uint32_t u; asm("cvt.rna.tf32.f32 %0, %1;" : "=r"(u) : "f"(v));
    return __uint_as_float(u);
}
__device__ __forceinline__ float sigm(float x) {
    return __fdividef(1.f, 1.f + __expf(-x));
}

// ============================ stage load (global -> smem, swizzled) ========
// smem element (row r, k) lives at float offset r*32 + (k ^ ((r&7)<<2)).
template<int KDIM>
__device__ __forceinline__ void stage_load(
    const float* __restrict__ A, const float* __restrict__ B,
    int m0, int n0, int kc, int s, uint32_t sb, int tid)
{
    #pragma unroll
    for (int i = 0; i < 8; ++i) {                     // A: BM x BK = 2048 x 16B
        int id = tid + i * 256;
        int r = id >> 3, c = id & 7;
        uint32_t d = sb + (uint32_t)(s * STAGE_F + r * 32 + ((c * 4) ^ ((r & 7) << 2))) * 4u;
        cpa16(d, A + (size_t)(m0 + r) * KDIM + kc * BK + c * 4);
    }
    #pragma unroll
    for (int i = 0; i < 4; ++i) {                     // B: BN x BK = 1024 x 16B
        int id = tid + i * 256;
        int r = id >> 3, c = id & 7;
        uint32_t d = sb + (uint32_t)(s * STAGE_F + 8192 + r * 32 + ((c * 4) ^ ((r & 7) << 2))) * 4u;
        cpa16(d, B + (size_t)(n0 + r) * KDIM + kc * BK + c * 4);
    }
}

// ============================ main GEMM loop ===============================
// acc[mt][nt][4]: warp tile 64x64 as 4 m16 x 8 n8 mma tiles, k in chunks of 32.
template<int KDIM>
__device__ __forceinline__ void gemm_loop(
    float (&acc)[4][8][4],
    const float* __restrict__ A, const float* __restrict__ B,
    int m0, int n0, uint32_t sb, int tid, int lane, int wm, int wn)
{
    constexpr int NC = KDIM / BK;

    // ldmatrix per-lane address precompute.
    // lane L: matrix j = L>>3, row-in-matrix = L&7; swizzle s = (L&7)<<2.
    const int L7   = lane & 7;
    const int j    = lane >> 3;
    const int slow = (lane & 1) << 2;                 // s & 4
    const uint32_t perm = (uint32_t)((lane >> 1) & 3); // (s & 24) >> 3

    uint32_t preA[4], preB[4];
    {
        // A matrices: j=0:(rows+0,k+0) j=1:(rows+8,k+0) j=2:(rows+0,k+4) j=3:(rows+8,k+4)
        int rj  = ((j & 1) << 3) + L7;
        int c4a = (j >> 1) << 2;
        #pragma unroll
        for (int mt = 0; mt < 4; ++mt)
            preA[mt] = (uint32_t)(((wm * 64 + mt * 16 + rj) * 32 + (c4a ^ slow)) * 4);
        // B matrices (per nt-pair p): j=0:(nt,k0) j=1:(nt,k4) j=2:(nt+1,k0) j=3:(nt+1,k4)
        int c4b = (j & 1) << 2;
        #pragma unroll
        for (int p = 0; p < 4; ++p) {
            int nl = wn * 64 + (2 * p + (j >> 1)) * 8 + L7;
            preB[p] = (uint32_t)((8192 + nl * 32 + (c4b ^ slow)) * 4);
        }
    }

    stage_load<KDIM>(A, B, m0, n0, 0, 0, sb, tid);
    CP_COMMIT();

    #pragma unroll 1
    for (int c = 0; c < NC; ++c) {
        const int s = c & 1;
        if (c + 1 < NC) stage_load<KDIM>(A, B, m0, n0, c + 1, s ^ 1, sb, tid);
        CP_COMMIT();
        CP_WAIT1();
        __syncthreads();

        const uint32_t stg = sb + (uint32_t)s * STAGE_B;
        #pragma unroll 1
        for (int ks = 0; ks < 4; ++ks) {
            const uint32_t u = ((uint32_t)ks ^ perm) << 5;  // swizzled k-step offset (bytes)
            uint32_t a[4][4], b[4][4];
            #pragma unroll
            for (int mt = 0; mt < 4; ++mt) ldsm4(a[mt], stg + preA[mt] + u);
            #pragma unroll
            for (int p = 0; p < 4; ++p)    ldsm4(b[p],  stg + preB[p] + u);
            #pragma unroll
            for (int mt = 0; mt < 4; ++mt) {
                #pragma unroll
                for (int p = 0; p < 4; ++p) {
                    mma8(acc[mt][2 * p],     a[mt], &b[p][0]);
                    mma8(acc[mt][2 * p + 1], a[mt], &b[p][2]);
                }
            }
        }
        __syncthreads();
    }
}

// ============================ fc1 fused ====================================
// C[256,128] = X @ W1^T tile; epilogue: sigmoid(C+b1) -> grouped dot with W2
// (quad shfl reduction; 8 cols per group) -> sigmoid -> x2 (tf32-rounded).
__global__ void __launch_bounds__(256, 1) fc1_kernel(
    const float* __restrict__ X,  const float* __restrict__ W1,
    const float* __restrict__ b1, const float* __restrict__ W2,
    const float* __restrict__ b2, float* __restrict__ x2)
{
    extern __shared__ float sm[];
    const uint32_t sb = sm32(sm);
    const int tid = threadIdx.x, lane = tid & 31, wid = tid >> 5;
    const int wm = wid & 3, wn = wid >> 2;
    const int m0 = blockIdx.y * BM, n0 = blockIdx.x * BN;

    float* b1s = sm + 2 * STAGE_F;
    float* w2s = b1s + BN;
    float* b2s = w2s + BN;
    if (tid < BN) { b1s[tid] = b1[n0 + tid]; w2s[tid] = W2[n0 + tid]; }
    if (tid < 16) b2s[tid] = b2[blockIdx.x * 16 + tid];

    float acc[4][8][4];
    #pragma unroll
    for (int i = 0; i < 4; ++i)
        #pragma unroll
        for (int j2 = 0; j2 < 8; ++j2)
            #pragma unroll
            for (int k = 0; k < 4; ++k) acc[i][j2][k] = 0.f;

    gemm_loop<D_IN>(acc, X, W1, m0, n0, sb, tid, lane, wm, wn);

    // -------- fused epilogue --------
    const int q = lane & 3, g2 = lane >> 2;
    float* es = sm;                                   // reuse stage0 A; stride 20 (pad)
    #pragma unroll
    for (int mt = 0; mt < 4; ++mt) {
        #pragma unroll
        for (int nt = 0; nt < 8; ++nt) {
            int cl = wn * 64 + nt * 8 + 2 * q;        // CTA-local column
            float h00 = sigm(acc[mt][nt][0] + b1s[cl]);
            float h01 = sigm(acc[mt][nt][1] + b1s[cl + 1]);
            float h10 = sigm(acc[mt][nt][2] + b1s[cl]);
            float h11 = sigm(acc[mt][nt][3] + b1s[cl + 1]);
            float p0 = h00 * w2s[cl] + h01 * w2s[cl + 1];
            float p1 = h10 * w2s[cl] + h11 * w2s[cl + 1];
            p0 += __shfl_xor_sync(0xffffffffu, p0, 1);
            p0 += __shfl_xor_sync(0xffffffffu, p0, 2);
            p1 += __shfl_xor_sync(0xffffffffu, p1, 1);
            p1 += __shfl_xor_sync(0xffffffffu, p1, 2);
            if (q == (nt & 3)) {
                int g  = wn * 8 + nt;                 // CTA-local group (16 per CTA)
                int r0 = wm * 64 + mt * 16 + g2;
                es[r0 * 20 + g]       = rna_tf32(sigm(p0 + b2s[g]));
                es[(r0 + 8) * 20 + g] = rna_tf32(sigm(p1 + b2s[g]));
            }
        }
    }
    __syncthreads();

    // coalesced store: 256 rows x 16 groups
    #pragma unroll
    for (int i = 0; i < 4; ++i) {
        int id = tid + i * 256;
        int r = id >> 2, c4 = (id & 3) * 4;
        float4 v = *(const float4*)(es + r * 20 + c4);
        *(float4*)(x2 + (size_t)(m0 + r) * NH2 + blockIdx.x * 16 + c4) = v;
    }
}

// ============================ fc3: out = x2 @ W3^T + b3 ====================
__global__ void __launch_bounds__(256, 1) fc3_kernel(
    const float* __restrict__ A,  const float* __restrict__ W3,
    const float* __restrict__ b3, float* __restrict__ out)
{
    extern __shared__ float sm[];
    const uint32_t sb = sm32(sm);
    const int tid = threadIdx.x, lane = tid & 31, wid = tid >> 5;
    const int wm = wid & 3, wn = wid >> 2;
    const int m0 = blockIdx.y * BM, n0 = blockIdx.x * BN;

    float* b3s = sm + 2 * STAGE_F;
    if (tid < BN) b3s[tid] = b3[n0 + tid];

    float acc[4][8][4];
    #pragma unroll
    for (int i = 0; i < 4; ++i)
        #pragma unroll
        for (int j2 = 0; j2 < 8; ++j2)
            #pragma unroll
            for (int k = 0; k < 4; ++k) acc[i][j2][k] = 0.f;

    gemm_loop<NH2>(acc, A, W3, m0, n0, sb, tid, lane, wm, wn);

    const int q = lane & 3, g2 = lane >> 2;
    #pragma unroll
    for (int mt = 0; mt < 4; ++mt) {
        #pragma unroll
        for (int nt = 0; nt < 8; ++nt) {
            int cl = wn * 64 + nt * 8 + 2 * q;
            int r0 = m0 + wm * 64 + mt * 16 + g2;
            float2 v0 = make_float2(acc[mt][nt][0] + b3s[cl], acc[mt][nt][1] + b3s[cl + 1]);
            float2 v1 = make_float2(acc[mt][nt][2] + b3s[cl], acc[mt][nt][3] + b3s[cl + 1]);
            *(float2*)(out + (size_t)r0 * D_OUT + n0 + cl)       = v0;
            *(float2*)(out + (size_t)(r0 + 8) * D_OUT + n0 + cl) = v1;
        }
    }
}

// ============================ host =========================================
extern "C" void kernel_launch(void* const* d_in, const int* in_sizes, int n_in,
                              void* d_out, int out_size) {
    (void)in_sizes; (void)n_in; (void)out_size;
    const float* x  = (const float*)d_in[0];
    const float* W1 = (const float*)d_in[1];
    const float* b1 = (const float*)d_in[2];
    const float* W2 = (const float*)d_in[3];
    const float* b2 = (const float*)d_in[4];
    const float* W3 = (const float*)d_in[5];
    const float* b3 = (const float*)d_in[6];
    float* out = (float*)d_out;

    void* px2 = nullptr;
    cudaGetSymbolAddress(&px2, g_x2);

    const int smem1 = (2 * STAGE_F + 2 * BN + 16) * 4;   // 99392 B
    const int smem3 = (2 * STAGE_F + BN) * 4;            // 98816 B
    cudaFuncSetAttribute(fc1_kernel, cudaFuncAttributeMaxDynamicSharedMemorySize, smem1);
    cudaFuncSetAttribute(fc3_kernel, cudaFuncAttributeMaxDynamicSharedMemorySize, smem3);

    // fc1 fused: grid x = n-tiles (fast-varying -> wave shares X tiles in L2)
    fc1_kernel<<<dim3(NH1 / BN, NROWS / BM), 256, smem1>>>(
        x, W1, b1, W2, b2, (float*)px2);
    // fc3
    fc3_kernel<<<dim3(D_OUT / BN, NROWS / BM), 256, smem3>>>(
        (const float*)px2, W3, b3, out);
}

// round 3
// speedup vs baseline: 1.6014x; 1.6014x over previous
#include <cuda_runtime.h>
#include <cuda_fp16.h>
#include <cstdint>
#include <cstddef>

// ============================ problem constants ============================
#define D_IN   1024
#define NH1    4096
#define NH2    512
#define D_OUT  256
#define NROWS  16384

// ============================ tiling =======================================
#define BM 256
#define BN 128
#define BK 64                      // fp16: row = 128B
#define STAGE_B 49152              // (BM+BN)*BK*2 bytes per stage

// ============================ scratch ======================================
__device__ __align__(1024) __half g_Xh [NROWS * D_IN];   // fp16 X
__device__ __align__(1024) __half g_W1h[NH1 * D_IN];     // fp16 W1
__device__ __align__(1024) __half g_W3h[D_OUT * NH2];    // fp16 W3
__device__ __align__(1024) __half g_x2h[NROWS * NH2];    // fp16 grouped output

// ============================ device helpers ===============================
__device__ __forceinline__ uint32_t sm32(const void* p) {
    uint32_t a;
    asm("{ .reg .u64 t; cvta.to.shared.u64 t, %1; cvt.u32.u64 %0, t; }"
        : "=r"(a) : "l"(p));
    return a;
}
__device__ __forceinline__ void cpa16(uint32_t d, const void* s) {
    asm volatile("cp.async.cg.shared.global [%0], [%1], 16;" :: "r"(d), "l"(s));
}
#define CP_COMMIT() asm volatile("cp.async.commit_group;" ::: "memory")
#define CP_WAIT1()  asm volatile("cp.async.wait_group 1;" ::: "memory")

__device__ __forceinline__ void ldsm4(uint32_t* d, uint32_t a) {
    asm volatile("ldmatrix.sync.aligned.m8n8.x4.shared.b16 {%0,%1,%2,%3}, [%4];"
        : "=r"(d[0]), "=r"(d[1]), "=r"(d[2]), "=r"(d[3]) : "r"(a));
}
__device__ __forceinline__ void mma16(float* c, const uint32_t* a, const uint32_t* b) {
    asm volatile("mma.sync.aligned.m16n8k16.row.col.f32.f16.f16.f32 "
        "{%0,%1,%2,%3}, {%4,%5,%6,%7}, {%8,%9}, {%0,%1,%2,%3};"
        : "+f"(c[0]), "+f"(c[1]), "+f"(c[2]), "+f"(c[3])
        : "r"(a[0]), "r"(a[1]), "r"(a[2]), "r"(a[3]), "r"(b[0]), "r"(b[1]));
}
__device__ __forceinline__ float sigm(float x) {
    return __fdividef(1.f, 1.f + __expf(-x));
}

// ============================ fp32 -> fp16 convert =========================
__global__ void cvt_kernel(const float4* __restrict__ s, uint2* __restrict__ d, int n4) {
    int i = blockIdx.x * blockDim.x + threadIdx.x;
    if (i < n4) {
        float4 v = s[i];
        __half2 h0 = __floats2half2_rn(v.x, v.y);
        __half2 h1 = __floats2half2_rn(v.z, v.w);
        uint2 o;
        o.x = *(uint32_t*)&h0;
        o.y = *(uint32_t*)&h1;
        d[i] = o;
    }
}

// ============================ stage load (global -> smem, swizzled) ========
// element (row r, k): byte = r*128 + (((k>>3) ^ (r&7))<<4) + (k&7)*2
template<int KDIM>
__device__ __forceinline__ void stage_load(
    const __half* __restrict__ A, const __half* __restrict__ B,
    int m0, int n0, int kc, int s, uint32_t sb, int tid)
{
    #pragma unroll
    for (int i = 0; i < 8; ++i) {                 // A: 256 rows x 8 units
        int id = tid + i * 256;
        int r = id >> 3, u = id & 7;
        uint32_t d = sb + (uint32_t)(s * STAGE_B) + r * 128 + (((u ^ (r & 7))) << 4);
        cpa16(d, A + (size_t)(m0 + r) * KDIM + kc * BK + u * 8);
    }
    #pragma unroll
    for (int i = 0; i < 4; ++i) {                 // B: 128 rows x 8 units
        int id = tid + i * 256;
        int r = id >> 3, u = id & 7;
        uint32_t d = sb + (uint32_t)(s * STAGE_B) + 32768 + r * 128 + (((u ^ (r & 7))) << 4);
        cpa16(d, B + (size_t)(n0 + r) * KDIM + kc * BK + u * 8);
    }
}

// ============================ main GEMM loop (fp16) ========================
// warp tile 64x64: 4 m16 tiles x 8 n8 tiles; k in chunks of 64 (4 k16 steps).
template<int KDIM>
__device__ __forceinline__ void gemm_loop(
    float (&acc)[4][8][4],
    const __half* __restrict__ A, const __half* __restrict__ B,
    int m0, int n0, uint32_t sb, int tid, int lane, int wm, int wn)
{
    constexpr int NC = KDIM / BK;
    const int lr = lane & 7, j = lane >> 3;
    const int jlow = j & 1, jhi = j >> 1;

    uint32_t baseA[4], baseB[4];
    #pragma unroll
    for (int mt = 0; mt < 4; ++mt)
        baseA[mt] = (uint32_t)((wm * 64 + mt * 16 + (jlow << 3) + lr) * 128);
    #pragma unroll
    for (int p = 0; p < 4; ++p)
        baseB[p] = (uint32_t)(32768 + (wn * 64 + (2 * p + jhi) * 8 + lr) * 128);

    stage_load<KDIM>(A, B, m0, n0, 0, 0, sb, tid);
    CP_COMMIT();

    #pragma unroll 1
    for (int c = 0; c < NC; ++c) {
        const int s = c & 1;
        if (c + 1 < NC) stage_load<KDIM>(A, B, m0, n0, c + 1, s ^ 1, sb, tid);
        CP_COMMIT();
        CP_WAIT1();
        __syncthreads();

        const uint32_t stg = sb + (uint32_t)s * STAGE_B;
        #pragma unroll
        for (int ks = 0; ks < 4; ++ks) {
            const uint32_t swzA = (uint32_t)(((2 * ks + jhi) ^ lr) << 4);
            const uint32_t swzB = (uint32_t)(((2 * ks + jlow) ^ lr) << 4);
            uint32_t a[4][4], b[4][4];
            #pragma unroll
            for (int mt = 0; mt < 4; ++mt) ldsm4(a[mt], stg + baseA[mt] + swzA);
            #pragma unroll
            for (int p = 0; p < 4; ++p)    ldsm4(b[p],  stg + baseB[p] + swzB);
            #pragma unroll
            for (int mt = 0; mt < 4; ++mt) {
                #pragma unroll
                for (int p = 0; p < 4; ++p) {
                    mma16(acc[mt][2 * p],     a[mt], &b[p][0]);
                    mma16(acc[mt][2 * p + 1], a[mt], &b[p][2]);
                }
            }
        }
        __syncthreads();
    }
}

// ============================ fc1 fused ====================================
// C[256,128] = X @ W1^T tile; epilogue: sigmoid(C+b1) -> grouped dot with W2
// (quad shfl reduction; 8 cols per group) -> sigmoid -> x2 (fp16).
__global__ void __launch_bounds__(256, 1) fc1_kernel(
    const __half* __restrict__ X,  const __half* __restrict__ W1,
    const float* __restrict__ b1,  const float* __restrict__ W2,
    const float* __restrict__ b2,  __half* __restrict__ x2)
{
    extern __shared__ float sm[];
    const uint32_t sb = sm32(sm);
    const int tid = threadIdx.x, lane = tid & 31, wid = tid >> 5;
    const int wm = wid & 3, wn = wid >> 2;
    const int m0 = blockIdx.y * BM, n0 = blockIdx.x * BN;

    float* b1s = sm + 2 * STAGE_B / 4;
    float* w2s = b1s + BN;
    float* b2s = w2s + BN;
    if (tid < BN) { b1s[tid] = b1[n0 + tid]; w2s[tid] = W2[n0 + tid]; }
    if (tid < 16) b2s[tid] = b2[blockIdx.x * 16 + tid];

    float acc[4][8][4];
    #pragma unroll
    for (int i = 0; i < 4; ++i)
        #pragma unroll
        for (int j2 = 0; j2 < 8; ++j2)
            #pragma unroll
            for (int k = 0; k < 4; ++k) acc[i][j2][k] = 0.f;

    gemm_loop<D_IN>(acc, X, W1, m0, n0, sb, tid, lane, wm, wn);

    // -------- fused epilogue --------
    const int q = lane & 3, g2 = lane >> 2;
    float* es = sm;                               // reuse stage0; stride 20 (pad)
    #pragma unroll
    for (int mt = 0; mt < 4; ++mt) {
        #pragma unroll
        for (int nt = 0; nt < 8; ++nt) {
            int cl = wn * 64 + nt * 8 + 2 * q;    // CTA-local column
            float h00 = sigm(acc[mt][nt][0] + b1s[cl]);
            float h01 = sigm(acc[mt][nt][1] + b1s[cl + 1]);
            float h10 = sigm(acc[mt][nt][2] + b1s[cl]);
            float h11 = sigm(acc[mt][nt][3] + b1s[cl + 1]);
            float p0 = h00 * w2s[cl] + h01 * w2s[cl + 1];
            float p1 = h10 * w2s[cl] + h11 * w2s[cl + 1];
            p0 += __shfl_xor_sync(0xffffffffu, p0, 1);
            p0 += __shfl_xor_sync(0xffffffffu, p0, 2);
            p1 += __shfl_xor_sync(0xffffffffu, p1, 1);
            p1 += __shfl_xor_sync(0xffffffffu, p1, 2);
            if (q == (nt & 3)) {
                int g  = wn * 8 + nt;             // CTA-local group (16 per CTA)
                int r0 = wm * 64 + mt * 16 + g2;
                es[r0 * 20 + g]       = sigm(p0 + b2s[g]);
                es[(r0 + 8) * 20 + g] = sigm(p1 + b2s[g]);
            }
        }
    }
    __syncthreads();

    // coalesced fp16 store: 256 rows x 16 groups
    #pragma unroll
    for (int i = 0; i < 2; ++i) {
        int id = tid + i * 256;
        int r = id >> 1, c8 = (id & 1) * 8;
        const float* e = es + r * 20 + c8;
        __half2 h0 = __floats2half2_rn(e[0], e[1]);
        __half2 h1 = __floats2half2_rn(e[2], e[3]);
        __half2 h2 = __floats2half2_rn(e[4], e[5]);
        __half2 h3 = __floats2half2_rn(e[6], e[7]);
        uint4 o;
        o.x = *(uint32_t*)&h0; o.y = *(uint32_t*)&h1;
        o.z = *(uint32_t*)&h2; o.w = *(uint32_t*)&h3;
        *(uint4*)(x2 + (size_t)(m0 + r) * NH2 + blockIdx.x * 16 + c8) = o;
    }
}

// ============================ fc3: out = x2 @ W3^T + b3 ====================
__global__ void __launch_bounds__(256, 1) fc3_kernel(
    const __half* __restrict__ A,  const __half* __restrict__ W3,
    const float* __restrict__ b3,  float* __restrict__ out)
{
    extern __shared__ float sm[];
    const uint32_t sb = sm32(sm);
    const int tid = threadIdx.x, lane = tid & 31, wid = tid >> 5;
    const int wm = wid & 3, wn = wid >> 2;
    const int m0 = blockIdx.y * BM, n0 = blockIdx.x * BN;

    float* b3s = sm + 2 * STAGE_B / 4;
    if (tid < BN) b3s[tid] = b3[n0 + tid];

    float acc[4][8][4];
    #pragma unroll
    for (int i = 0; i < 4; ++i)
        #pragma unroll
        for (int j2 = 0; j2 < 8; ++j2)
            #pragma unroll
            for (int k = 0; k < 4; ++k) acc[i][j2][k] = 0.f;

    gemm_loop<NH2>(acc, A, W3, m0, n0, sb, tid, lane, wm, wn);

    const int q = lane & 3, g2 = lane >> 2;
    #pragma unroll
    for (int mt = 0; mt < 4; ++mt) {
        #pragma unroll
        for (int nt = 0; nt < 8; ++nt) {
            int cl = wn * 64 + nt * 8 + 2 * q;
            int r0 = m0 + wm * 64 + mt * 16 + g2;
            float2 v0 = make_float2(acc[mt][nt][0] + b3s[cl], acc[mt][nt][1] + b3s[cl + 1]);
            float2 v1 = make_float2(acc[mt][nt][2] + b3s[cl], acc[mt][nt][3] + b3s[cl + 1]);
            *(float2*)(out + (size_t)r0 * D_OUT + n0 + cl)       = v0;
            *(float2*)(out + (size_t)(r0 + 8) * D_OUT + n0 + cl) = v1;
        }
    }
}

// ============================ host =========================================
extern "C" void kernel_launch(void* const* d_in, const int* in_sizes, int n_in,
                              void* d_out, int out_size) {
    (void)in_sizes; (void)n_in; (void)out_size;
    const float* x  = (const float*)d_in[0];
    const float* W1 = (const float*)d_in[1];
    const float* b1 = (const float*)d_in[2];
    const float* W2 = (const float*)d_in[3];
    const float* b2 = (const float*)d_in[4];
    const float* W3 = (const float*)d_in[5];
    const float* b3 = (const float*)d_in[6];
    float* out = (float*)d_out;

    void *pXh = nullptr, *pW1h = nullptr, *pW3h = nullptr, *px2h = nullptr;
    cudaGetSymbolAddress(&pXh,  g_Xh);
    cudaGetSymbolAddress(&pW1h, g_W1h);
    cudaGetSymbolAddress(&pW3h, g_W3h);
    cudaGetSymbolAddress(&px2h, g_x2h);

    const int smem1 = 2 * STAGE_B + (2 * BN + 16) * 4;   // 99392 B
    const int smem3 = 2 * STAGE_B + BN * 4;              // 98816 B
    cudaFuncSetAttribute(fc1_kernel, cudaFuncAttributeMaxDynamicSharedMemorySize, smem1);
    cudaFuncSetAttribute(fc3_kernel, cudaFuncAttributeMaxDynamicSharedMemorySize, smem3);

    // fp32 -> fp16 converts
    {
        int n4 = NROWS * D_IN / 4;
        cvt_kernel<<<(n4 + 255) / 256, 256>>>((const float4*)x, (uint2*)pXh, n4);
        n4 = NH1 * D_IN / 4;
        cvt_kernel<<<(n4 + 255) / 256, 256>>>((const float4*)W1, (uint2*)pW1h, n4);
        n4 = D_OUT * NH2 / 4;
        cvt_kernel<<<(n4 + 255) / 256, 256>>>((const float4*)W3, (uint2*)pW3h, n4);
    }

    // fc1 fused: grid x = n-tiles (fast-varying -> wave shares X tiles in L2)
    fc1_kernel<<<dim3(NH1 / BN, NROWS / BM), 256, smem1>>>(
        (const __half*)pXh, (const __half*)pW1h, b1, W2, b2, (__half*)px2h);
    // fc3
    fc3_kernel<<<dim3(D_OUT / BN, NROWS / BM), 256, smem3>>>(
        (const __half*)px2h, (const __half*)pW3h, b3, out);
}

// round 4
// speedup vs baseline: 1.9562x; 1.2216x over previous
#include <cuda_runtime.h>
#include <cuda_fp16.h>
#include <cstdint>
#include <cstddef>

// ============================ problem constants ============================
#define D_IN   1024
#define NH1    4096
#define NH2    512
#define D_OUT  256
#define NROWS  16384

// ============================ tiling =======================================
#define BM 128
#define BN 128
#define BK 64                        // fp16: row = 128B
#define NSTG 3
#define STAGE_B 32768                // (BM+BN)*BK*2 bytes
#define B_OFF   16384                // A tile bytes within a stage

// ============================ scratch ======================================
__device__ __align__(1024) __half g_Xh [NROWS * D_IN];
__device__ __align__(1024) __half g_W1h[NH1 * D_IN];
__device__ __align__(1024) __half g_W3h[D_OUT * NH2];
__device__ __align__(1024) __half g_x2h[NROWS * NH2];

// ============================ device helpers ===============================
__device__ __forceinline__ uint32_t sm32(const void* p) {
    uint32_t a;
    asm("{ .reg .u64 t; cvta.to.shared.u64 t, %1; cvt.u32.u64 %0, t; }"
        : "=r"(a) : "l"(p));
    return a;
}
__device__ __forceinline__ void cpa16(uint32_t d, const void* s) {
    asm volatile("cp.async.cg.shared.global [%0], [%1], 16;" :: "r"(d), "l"(s));
}
#define CP_COMMIT() asm volatile("cp.async.commit_group;" ::: "memory")
#define CP_WAIT1()  asm volatile("cp.async.wait_group 1;" ::: "memory")

__device__ __forceinline__ void ldsm4(uint32_t* d, uint32_t a) {
    asm volatile("ldmatrix.sync.aligned.m8n8.x4.shared.b16 {%0,%1,%2,%3}, [%4];"
        : "=r"(d[0]), "=r"(d[1]), "=r"(d[2]), "=r"(d[3]) : "r"(a));
}
__device__ __forceinline__ void mma16(float* c, const uint32_t* a, const uint32_t* b) {
    asm volatile("mma.sync.aligned.m16n8k16.row.col.f32.f16.f16.f32 "
        "{%0,%1,%2,%3}, {%4,%5,%6,%7}, {%8,%9}, {%0,%1,%2,%3};"
        : "+f"(c[0]), "+f"(c[1]), "+f"(c[2]), "+f"(c[3])
        : "r"(a[0]), "r"(a[1]), "r"(a[2]), "r"(a[3]), "r"(b[0]), "r"(b[1]));
}
__device__ __forceinline__ float sigm(float x) {
    return __fdividef(1.f, 1.f + __expf(-x));
}

// ============================ fp32 -> fp16 convert =========================
__global__ void cvt_kernel(const float4* __restrict__ s, uint2* __restrict__ d, int n4) {
    int i = blockIdx.x * blockDim.x + threadIdx.x;
    if (i < n4) {
        float4 v = s[i];
        __half2 h0 = __floats2half2_rn(v.x, v.y);
        __half2 h1 = __floats2half2_rn(v.z, v.w);
        uint2 o;
        o.x = *(uint32_t*)&h0;
        o.y = *(uint32_t*)&h1;
        d[i] = o;
    }
}

// ============================ stage load ===================================
// smem element (row r, k): byte = r*128 + (((k>>3) ^ (r&7))<<4) + (k&7)*2
template<int KDIM>
__device__ __forceinline__ void stage_load(
    const __half* __restrict__ A, const __half* __restrict__ B,
    int m0, int n0, int kc, int s, uint32_t sb, int tid)
{
    const uint32_t so = sb + (uint32_t)(s * STAGE_B);
    #pragma unroll
    for (int i = 0; i < 4; ++i) {                 // A: 128 rows x 8 x 16B
        int id = tid + i * 256;
        int r = id >> 3, u = id & 7;
        cpa16(so + r * 128 + ((u ^ (r & 7)) << 4),
              A + (size_t)(m0 + r) * KDIM + kc * BK + u * 8);
    }
    #pragma unroll
    for (int i = 0; i < 4; ++i) {                 // B: 128 rows x 8 x 16B
        int id = tid + i * 256;
        int r = id >> 3, u = id & 7;
        cpa16(so + B_OFF + r * 128 + ((u ^ (r & 7)) << 4),
              B + (size_t)(n0 + r) * KDIM + kc * BK + u * 8);
    }
}

// ============================ main GEMM loop (fp16) ========================
// 8 warps, warp tile 32x64: 2 m16 x 8 n8 mma tiles; BK=64 (4 k16 steps).
// 3-stage cp.async pipeline, ONE __syncthreads per chunk.
template<int KDIM>
__device__ __forceinline__ void gemm_loop(
    float (&acc)[2][8][4],
    const __half* __restrict__ A, const __half* __restrict__ B,
    int m0, int n0, uint32_t sb, int tid, int lane, int wm, int wn)
{
    constexpr int NC = KDIM / BK;
    const int lr = lane & 7, j = lane >> 3;
    const int jlow = j & 1, jhi = j >> 1;

    uint32_t baseA[2], baseB[4];
    #pragma unroll
    for (int mt = 0; mt < 2; ++mt)
        baseA[mt] = (uint32_t)((wm * 32 + mt * 16 + (jlow << 3) + lr) * 128);
    #pragma unroll
    for (int p = 0; p < 4; ++p)
        baseB[p] = (uint32_t)(B_OFF + (wn * 64 + (2 * p + jhi) * 8 + lr) * 128);

    stage_load<KDIM>(A, B, m0, n0, 0, 0, sb, tid);
    CP_COMMIT();
    stage_load<KDIM>(A, B, m0, n0, 1, 1, sb, tid);
    CP_COMMIT();

    int sc = 0;                                    // stage of chunk c
    int sn = 2;                                    // stage to fill next
    #pragma unroll 1
    for (int c = 0; c < NC; ++c) {
        CP_WAIT1();                                // chunk c resident
        __syncthreads();
        if (c + 2 < NC) stage_load<KDIM>(A, B, m0, n0, c + 2, sn, sb, tid);
        CP_COMMIT();

        const uint32_t stg = sb + (uint32_t)sc * STAGE_B;
        #pragma unroll
        for (int ks = 0; ks < 4; ++ks) {
            const uint32_t swzA = (uint32_t)(((2 * ks + jhi) ^ lr) << 4);
            const uint32_t swzB = (uint32_t)(((2 * ks + jlow) ^ lr) << 4);
            uint32_t a[2][4], b[4][4];
            #pragma unroll
            for (int mt = 0; mt < 2; ++mt) ldsm4(a[mt], stg + baseA[mt] + swzA);
            #pragma unroll
            for (int p = 0; p < 4; ++p)    ldsm4(b[p],  stg + baseB[p] + swzB);
            #pragma unroll
            for (int mt = 0; mt < 2; ++mt) {
                #pragma unroll
                for (int p = 0; p < 4; ++p) {
                    mma16(acc[mt][2 * p],     a[mt], &b[p][0]);
                    mma16(acc[mt][2 * p + 1], a[mt], &b[p][2]);
                }
            }
        }
        sc = (sc == NSTG - 1) ? 0 : sc + 1;
        sn = (sn == NSTG - 1) ? 0 : sn + 1;
    }
    __syncthreads();                               // protect smem reuse by epilogue
}

// ============================ fc1 fused ====================================
__global__ void __launch_bounds__(256, 2) fc1_kernel(
    const __half* __restrict__ X,  const __half* __restrict__ W1,
    const float* __restrict__ b1,  const float* __restrict__ W2,
    const float* __restrict__ b2,  __half* __restrict__ x2)
{
    extern __shared__ float sm[];
    const uint32_t sb = sm32(sm);
    const int tid = threadIdx.x, lane = tid & 31, wid = tid >> 5;
    const int wm = wid & 3, wn = wid >> 2;
    const int m0 = blockIdx.y * BM, n0 = blockIdx.x * BN;

    float* b1s = sm + NSTG * STAGE_B / 4;
    float* w2s = b1s + BN;
    float* b2s = w2s + BN;
    if (tid < BN) { b1s[tid] = b1[n0 + tid]; w2s[tid] = W2[n0 + tid]; }
    if (tid < 16) b2s[tid] = b2[blockIdx.x * 16 + tid];

    float acc[2][8][4];
    #pragma unroll
    for (int i = 0; i < 2; ++i)
        #pragma unroll
        for (int j2 = 0; j2 < 8; ++j2)
            #pragma unroll
            for (int k = 0; k < 4; ++k) acc[i][j2][k] = 0.f;

    gemm_loop<D_IN>(acc, X, W1, m0, n0, sb, tid, lane, wm, wn);

    // -------- fused epilogue: bias+sigmoid -> grouped dot (quad shfl) ------
    const int q = lane & 3, g2 = lane >> 2;
    float* es = sm;                                // reuse stage0; stride 20
    #pragma unroll
    for (int mt = 0; mt < 2; ++mt) {
        #pragma unroll
        for (int nt = 0; nt < 8; ++nt) {
            int cl = wn * 64 + nt * 8 + 2 * q;
            float h00 = sigm(acc[mt][nt][0] + b1s[cl]);
            float h01 = sigm(acc[mt][nt][1] + b1s[cl + 1]);
            float h10 = sigm(acc[mt][nt][2] + b1s[cl]);
            float h11 = sigm(acc[mt][nt][3] + b1s[cl + 1]);
            float p0 = h00 * w2s[cl] + h01 * w2s[cl + 1];
            float p1 = h10 * w2s[cl] + h11 * w2s[cl + 1];
            p0 += __shfl_xor_sync(0xffffffffu, p0, 1);
            p0 += __shfl_xor_sync(0xffffffffu, p0, 2);
            p1 += __shfl_xor_sync(0xffffffffu, p1, 1);
            p1 += __shfl_xor_sync(0xffffffffu, p1, 2);
            if (q == (nt & 3)) {
                int g  = wn * 8 + nt;              // 16 groups per CTA
                int r0 = wm * 32 + mt * 16 + g2;
                es[r0 * 20 + g]       = sigm(p0 + b2s[g]);
                es[(r0 + 8) * 20 + g] = sigm(p1 + b2s[g]);
            }
        }
    }
    __syncthreads();

    // coalesced fp16 store: 128 rows x 16 groups (one uint4 per thread... 2/row)
    {
        int r = tid >> 1, c8 = (tid & 1) * 8;
        const float* e = es + r * 20 + c8;
        __half2 h0 = __floats2half2_rn(e[0], e[1]);
        __half2 h1 = __floats2half2_rn(e[2], e[3]);
        __half2 h2 = __floats2half2_rn(e[4], e[5]);
        __half2 h3 = __floats2half2_rn(e[6], e[7]);
        uint4 o;
        o.x = *(uint32_t*)&h0; o.y = *(uint32_t*)&h1;
        o.z = *(uint32_t*)&h2; o.w = *(uint32_t*)&h3;
        *(uint4*)(x2 + (size_t)(m0 + r) * NH2 + blockIdx.x * 16 + c8) = o;
    }
}

// ============================ fc3 ==========================================
__global__ void __launch_bounds__(256, 2) fc3_kernel(
    const __half* __restrict__ A,  const __half* __restrict__ W3,
    const float* __restrict__ b3,  float* __restrict__ out)
{
    extern __shared__ float sm[];
    const uint32_t sb = sm32(sm);
    const int tid = threadIdx.x, lane = tid & 31, wid = tid >> 5;
    const int wm = wid & 3, wn = wid >> 2;
    const int m0 = blockIdx.y * BM, n0 = blockIdx.x * BN;

    float* b3s = sm + NSTG * STAGE_B / 4;
    if (tid < BN) b3s[tid] = b3[n0 + tid];

    float acc[2][8][4];
    #pragma unroll
    for (int i = 0; i < 2; ++i)
        #pragma unroll
        for (int j2 = 0; j2 < 8; ++j2)
            #pragma unroll
            for (int k = 0; k < 4; ++k) acc[i][j2][k] = 0.f;

    gemm_loop<NH2>(acc, A, W3, m0, n0, sb, tid, lane, wm, wn);

    const int q = lane & 3, g2 = lane >> 2;
    #pragma unroll
    for (int mt = 0; mt < 2; ++mt) {
        #pragma unroll
        for (int nt = 0; nt < 8; ++nt) {
            int cl = wn * 64 + nt * 8 + 2 * q;
            int r0 = m0 + wm * 32 + mt * 16 + g2;
            float2 v0 = make_float2(acc[mt][nt][0] + b3s[cl], acc[mt][nt][1] + b3s[cl + 1]);
            float2 v1 = make_float2(acc[mt][nt][2] + b3s[cl], acc[mt][nt][3] + b3s[cl + 1]);
            *(float2*)(out + (size_t)r0 * D_OUT + n0 + cl)       = v0;
            *(float2*)(out + (size_t)(r0 + 8) * D_OUT + n0 + cl) = v1;
        }
    }
}

// ============================ host =========================================
extern "C" void kernel_launch(void* const* d_in, const int* in_sizes, int n_in,
                              void* d_out, int out_size) {
    (void)in_sizes; (void)n_in; (void)out_size;
    const float* x  = (const float*)d_in[0];
    const float* W1 = (const float*)d_in[1];
    const float* b1 = (const float*)d_in[2];
    const float* W2 = (const float*)d_in[3];
    const float* b2 = (const float*)d_in[4];
    const float* W3 = (const float*)d_in[5];
    const float* b3 = (const float*)d_in[6];
    float* out = (float*)d_out;

    void *pXh = nullptr, *pW1h = nullptr, *pW3h = nullptr, *px2h = nullptr;
    cudaGetSymbolAddress(&pXh,  g_Xh);
    cudaGetSymbolAddress(&pW1h, g_W1h);
    cudaGetSymbolAddress(&pW3h, g_W3h);
    cudaGetSymbolAddress(&px2h, g_x2h);

    const int smem1 = NSTG * STAGE_B + (2 * BN + 16) * 4;   // 99392 B
    const int smem3 = NSTG * STAGE_B + BN * 4;              // 98816 B
    cudaFuncSetAttribute(fc1_kernel, cudaFuncAttributeMaxDynamicSharedMemorySize, smem1);
    cudaFuncSetAttribute(fc3_kernel, cudaFuncAttributeMaxDynamicSharedMemorySize, smem3);

    {
        int n4 = NROWS * D_IN / 4;
        cvt_kernel<<<(n4 + 255) / 256, 256>>>((const float4*)x, (uint2*)pXh, n4);
        n4 = NH1 * D_IN / 4;
        cvt_kernel<<<(n4 + 255) / 256, 256>>>((const float4*)W1, (uint2*)pW1h, n4);
        n4 = D_OUT * NH2 / 4;
        cvt_kernel<<<(n4 + 255) / 256, 256>>>((const float4*)W3, (uint2*)pW3h, n4);
    }

    fc1_kernel<<<dim3(NH1 / BN, NROWS / BM), 256, smem1>>>(
        (const __half*)pXh, (const __half*)pW1h, b1, W2, b2, (__half*)px2h);
    fc3_kernel<<<dim3(D_OUT / BN, NROWS / BM), 256, smem3>>>(
        (const __half*)px2h, (const __half*)pW3h, b3, out);
}